// round 1
// baseline (speedup 1.0000x reference)
#include <cuda_runtime.h>

// ---------------------------------------------------------------------------
// MultiheadAttention: out = ((softmax(mask(QK^T/32)) V) reshaped) @ Wo^T
// B=2, L=2048, D=1024, H=16, dh=64.
// Round 0: fp32 baseline. GEMMs: 64x64 tiles, 4x4 micro-tiles, k-major smem.
// Attention: flash-style, 64 q-rows x 64 k-cols tiles, online softmax.
// ---------------------------------------------------------------------------

namespace cfg {
constexpr int B = 2;
constexpr int L = 2048;
constexpr int D = 1024;
constexpr int H = 16;
constexpr int DH = 64;
constexpr int M = B * L;       // 4096 rows for projection GEMMs
constexpr int SMS = 68;        // smem row stride (floats), padded, 16B-aligned
}

// Scratch (allocation-free rule: __device__ globals)
__device__ float g_Q[(size_t)cfg::B * cfg::L * cfg::D];
__device__ float g_K[(size_t)cfg::B * cfg::L * cfg::D];
__device__ float g_V[(size_t)cfg::B * cfg::L * cfg::D];
__device__ float g_A[(size_t)cfg::B * cfg::L * cfg::D];

// ---------------------------------------------------------------------------
// C[M,N] = A[M,K] * W[N,K]^T with N = K = 1024 (torch Linear: y = x @ W.T)
// Block tile 64x64, k-step 16, 256 threads, each thread 4x4.
// ---------------------------------------------------------------------------
__global__ __launch_bounds__(256) void gemm_abt_kernel(
    const float* __restrict__ A, const float* __restrict__ W,
    float* __restrict__ C) {
  using namespace cfg;
  __shared__ float As[16 * SMS];  // k-major: As[k][row]
  __shared__ float Ws[16 * SMS];  // k-major: Ws[k][col]

  const int tid = threadIdx.x;
  const int r0 = (tid >> 4) << 2;   // 0..60 (micro-tile rows)
  const int c0 = (tid & 15) << 2;   // 0..60 (micro-tile cols)
  const int bm = blockIdx.y << 6;
  const int bn = blockIdx.x << 6;

  // per-thread load slot: one float4 of A and of W per k-step
  const int lr = tid >> 2;          // 0..63 row within tile
  const int lk = (tid & 3) << 2;    // 0,4,8,12 k-offset

  const float* Ap = A + (size_t)(bm + lr) * D + lk;
  const float* Wp = W + (size_t)(bn + lr) * D + lk;

  float acc[4][4] = {};

  for (int k0 = 0; k0 < D; k0 += 16) {
    float4 a4 = *(const float4*)(Ap + k0);
    float4 w4 = *(const float4*)(Wp + k0);
    __syncthreads();
    As[(lk + 0) * SMS + lr] = a4.x;
    As[(lk + 1) * SMS + lr] = a4.y;
    As[(lk + 2) * SMS + lr] = a4.z;
    As[(lk + 3) * SMS + lr] = a4.w;
    Ws[(lk + 0) * SMS + lr] = w4.x;
    Ws[(lk + 1) * SMS + lr] = w4.y;
    Ws[(lk + 2) * SMS + lr] = w4.z;
    Ws[(lk + 3) * SMS + lr] = w4.w;
    __syncthreads();
#pragma unroll
    for (int kk = 0; kk < 16; ++kk) {
      float4 av4 = *(const float4*)(As + kk * SMS + r0);
      float4 wv4 = *(const float4*)(Ws + kk * SMS + c0);
      float av[4] = {av4.x, av4.y, av4.z, av4.w};
      float wv[4] = {wv4.x, wv4.y, wv4.z, wv4.w};
#pragma unroll
      for (int i = 0; i < 4; ++i)
#pragma unroll
        for (int j = 0; j < 4; ++j)
          acc[i][j] = fmaf(av[i], wv[j], acc[i][j]);
    }
  }

#pragma unroll
  for (int i = 0; i < 4; ++i) {
    float4 o = make_float4(acc[i][0], acc[i][1], acc[i][2], acc[i][3]);
    *(float4*)(C + (size_t)(bm + r0 + i) * D + bn + c0) = o;
  }
}

// ---------------------------------------------------------------------------
// Flash attention over g_Q/g_K/g_V -> g_A.
// grid = (L/64, H, B), block = 256 threads.
// smem: Qs (d-major [d][row]), Ks (d-major [d][col]), Vs (row-major [j][d]),
//       Ps ([j][row]), kpm_s[64].
// Thread owns rows r0..r0+3 and cols c0..c0+3 (S) / dcols c0..c0+3 (O).
// ---------------------------------------------------------------------------
__global__ __launch_bounds__(256) void attn_kernel(
    const float* __restrict__ attn_mask, const int* __restrict__ kpm) {
  using namespace cfg;
  extern __shared__ float sm[];
  float* Qs = sm;                     // [64][SMS] transposed
  float* Ks = sm + 64 * SMS;          // [64][SMS] transposed
  float* Vs = sm + 2 * 64 * SMS;      // [64][SMS] row-major
  float* Ps = sm + 3 * 64 * SMS;      // [64][SMS] [j][row]
  int* kpm_s = (int*)(sm + 4 * 64 * SMS);

  const int tid = threadIdx.x;
  const int qt = blockIdx.x;   // q tile 0..31
  const int h = blockIdx.y;
  const int b = blockIdx.z;
  const int r0 = (tid >> 4) << 2;
  const int c0 = (tid & 15) << 2;

  const float* Qg = g_Q + (size_t)(b * L + qt * 64) * D + h * DH;
  const float* Kg = g_K + (size_t)b * L * D + h * DH;
  const float* Vg = g_V + (size_t)b * L * D + h * DH;

  // Load Q tile, transposed to d-major.
#pragma unroll
  for (int t = 0; t < 4; ++t) {
    int idx = tid + t * 256;
    int row = idx >> 4;
    int d = (idx & 15) << 2;
    float4 q4 = *(const float4*)(Qg + (size_t)row * D + d);
    Qs[(d + 0) * SMS + row] = q4.x;
    Qs[(d + 1) * SMS + row] = q4.y;
    Qs[(d + 2) * SMS + row] = q4.z;
    Qs[(d + 3) * SMS + row] = q4.w;
  }

  float mrun[4], lrun[4], O[4][4];
#pragma unroll
  for (int i = 0; i < 4; ++i) {
    mrun[i] = -1e30f;
    lrun[i] = 0.0f;
#pragma unroll
    for (int q = 0; q < 4; ++q) O[i][q] = 0.0f;
  }

  const float scale = 0.03125f;  // 1/sqrt(1024)

  for (int kt = 0; kt < 32; ++kt) {
    __syncthreads();  // previous iteration's readers of Ks/Vs/Ps/kpm_s done
    // Load K (transposed) and V (row-major) tiles + padding mask.
#pragma unroll
    for (int t = 0; t < 4; ++t) {
      int idx = tid + t * 256;
      int row = idx >> 4;
      int d = (idx & 15) << 2;
      float4 k4 = *(const float4*)(Kg + (size_t)(kt * 64 + row) * D + d);
      Ks[(d + 0) * SMS + row] = k4.x;
      Ks[(d + 1) * SMS + row] = k4.y;
      Ks[(d + 2) * SMS + row] = k4.z;
      Ks[(d + 3) * SMS + row] = k4.w;
      float4 v4 = *(const float4*)(Vg + (size_t)(kt * 64 + row) * D + d);
      *(float4*)(Vs + row * SMS + d) = v4;
    }
    if (tid < 64) kpm_s[tid] = kpm[b * L + kt * 64 + tid];
    __syncthreads();

    // S = Q K^T for this tile (4x4 per thread).
    float s[4][4] = {};
#pragma unroll 16
    for (int d = 0; d < 64; ++d) {
      float4 aq = *(const float4*)(Qs + d * SMS + r0);
      float4 kq = *(const float4*)(Ks + d * SMS + c0);
      float av[4] = {aq.x, aq.y, aq.z, aq.w};
      float kv[4] = {kq.x, kq.y, kq.z, kq.w};
#pragma unroll
      for (int i = 0; i < 4; ++i)
#pragma unroll
        for (int j = 0; j < 4; ++j)
          s[i][j] = fmaf(av[i], kv[j], s[i][j]);
    }

    // Epilogue: scale + attn_mask + key_padding_mask, online softmax update.
    const int rowg = qt * 64 + r0;
    const int colg = kt * 64 + c0;
    bool pad[4];
#pragma unroll
    for (int j = 0; j < 4; ++j) pad[j] = (kpm_s[c0 + j] == 0);

#pragma unroll
    for (int i = 0; i < 4; ++i) {
      const float* mrow = attn_mask + (size_t)(rowg + i) * L + colg;
      float sv[4];
#pragma unroll
      for (int j = 0; j < 4; ++j)
        sv[j] = pad[j] ? -1e7f : fmaf(s[i][j], scale, mrow[j]);

      float mx = fmaxf(fmaxf(sv[0], sv[1]), fmaxf(sv[2], sv[3]));
#pragma unroll
      for (int off = 8; off >= 1; off >>= 1)
        mx = fmaxf(mx, __shfl_xor_sync(0xffffffffu, mx, off));

      float mnew = fmaxf(mrun[i], mx);
      float alpha = __expf(mrun[i] - mnew);
      float psum = 0.0f;
#pragma unroll
      for (int j = 0; j < 4; ++j) {
        float p = __expf(sv[j] - mnew);
        psum += p;
        Ps[(c0 + j) * SMS + r0 + i] = p;
      }
#pragma unroll
      for (int off = 8; off >= 1; off >>= 1)
        psum += __shfl_xor_sync(0xffffffffu, psum, off);

      lrun[i] = lrun[i] * alpha + psum;
      mrun[i] = mnew;
#pragma unroll
      for (int q = 0; q < 4; ++q) O[i][q] *= alpha;
    }
    __syncthreads();  // Ps fully written

    // O += P V (4 rows x 4 dcols per thread).
#pragma unroll 16
    for (int j = 0; j < 64; ++j) {
      float4 p4 = *(const float4*)(Ps + j * SMS + r0);
      float4 v4 = *(const float4*)(Vs + j * SMS + c0);
      float pv[4] = {p4.x, p4.y, p4.z, p4.w};
      float vv[4] = {v4.x, v4.y, v4.z, v4.w};
#pragma unroll
      for (int i = 0; i < 4; ++i)
#pragma unroll
        for (int q = 0; q < 4; ++q)
          O[i][q] = fmaf(pv[i], vv[q], O[i][q]);
    }
  }

  // Normalize and write to g_A in [b, l, h, dh] layout.
  float* Og = g_A + (size_t)(b * L + qt * 64) * D + h * DH;
#pragma unroll
  for (int i = 0; i < 4; ++i) {
    float inv = 1.0f / lrun[i];
    float4 o = make_float4(O[i][0] * inv, O[i][1] * inv,
                           O[i][2] * inv, O[i][3] * inv);
    *(float4*)(Og + (size_t)(r0 + i) * D + c0) = o;
  }
}

// ---------------------------------------------------------------------------
extern "C" void kernel_launch(void* const* d_in, const int* in_sizes, int n_in,
                              void* d_out, int out_size) {
  using namespace cfg;
  (void)in_sizes; (void)n_in; (void)out_size;

  const float* query = (const float*)d_in[0];
  const float* key   = (const float*)d_in[1];
  const float* value = (const float*)d_in[2];
  const int* kpm     = (const int*)d_in[3];
  const float* mask  = (const float*)d_in[4];
  const float* Wq    = (const float*)d_in[5];
  const float* Wk    = (const float*)d_in[6];
  const float* Wv    = (const float*)d_in[7];
  const float* Wo    = (const float*)d_in[8];
  float* out = (float*)d_out;

  float *Qp, *Kp, *Vp, *Ap;
  cudaGetSymbolAddress((void**)&Qp, g_Q);
  cudaGetSymbolAddress((void**)&Kp, g_K);
  cudaGetSymbolAddress((void**)&Vp, g_V);
  cudaGetSymbolAddress((void**)&Ap, g_A);

  dim3 gg(D / 64, M / 64);  // (16, 64)
  gemm_abt_kernel<<<gg, 256>>>(query, Wq, Qp);
  gemm_abt_kernel<<<gg, 256>>>(key,   Wk, Kp);
  gemm_abt_kernel<<<gg, 256>>>(value, Wv, Vp);

  const int smem = 4 * 64 * SMS * (int)sizeof(float) + 64 * (int)sizeof(int);
  cudaFuncSetAttribute(attn_kernel,
                       cudaFuncAttributeMaxDynamicSharedMemorySize, smem);
  attn_kernel<<<dim3(L / 64, H, B), 256, smem>>>(mask, kpm);

  gemm_abt_kernel<<<gg, 256>>>(Ap, Wo, out);
}

// round 3
// speedup vs baseline: 1.4363x; 1.4363x over previous
#include <cuda_runtime.h>
#include <cuda_bf16.h>
#include <cstdint>

// ---------------------------------------------------------------------------
// MHA: B=2, L=2048, D=1024, H=16, dh=64.
// R2: projection GEMMs on mma.sync bf16 (hi/lo 3-pass split), target sm_100
//     (plain) — tcgen05 unavailable in this toolchain. Attention: fp32 SIMT.
// ---------------------------------------------------------------------------

namespace cfg {
constexpr int B = 2;
constexpr int L = 2048;
constexpr int D = 1024;
constexpr int H = 16;
constexpr int DH = 64;
constexpr int M = B * L;       // 4096
constexpr int SMS = 68;        // attn smem stride (floats)
}

__device__ float g_Q[(size_t)cfg::B * cfg::L * cfg::D];
__device__ float g_K[(size_t)cfg::B * cfg::L * cfg::D];
__device__ float g_V[(size_t)cfg::B * cfg::L * cfg::D];
__device__ float g_A[(size_t)cfg::B * cfg::L * cfg::D];

// ======================= portable tensor-core helpers ======================
__device__ __forceinline__ uint32_t smem_u32(const void* p) {
  uint32_t a;
  asm("{ .reg .u64 t; cvta.to.shared.u64 t, %1; cvt.u32.u64 %0, t; }"
      : "=r"(a) : "l"(p));
  return a;
}

__device__ __forceinline__ void ldm_x4(uint32_t& r0, uint32_t& r1,
                                       uint32_t& r2, uint32_t& r3,
                                       uint32_t addr) {
  asm volatile("ldmatrix.sync.aligned.m8n8.x4.shared.b16 {%0,%1,%2,%3}, [%4];"
               : "=r"(r0), "=r"(r1), "=r"(r2), "=r"(r3) : "r"(addr));
}

__device__ __forceinline__ void mma_bf16(float* c, const uint32_t* a,
                                         const uint32_t* b) {
  asm volatile(
      "mma.sync.aligned.m16n8k16.row.col.f32.bf16.bf16.f32 "
      "{%0,%1,%2,%3}, {%4,%5,%6,%7}, {%8,%9}, {%0,%1,%2,%3};"
      : "+f"(c[0]), "+f"(c[1]), "+f"(c[2]), "+f"(c[3])
      : "r"(a[0]), "r"(a[1]), "r"(a[2]), "r"(a[3]), "r"(b[0]), "r"(b[1]));
}

#define SW128(off) ((off) ^ ((((uint32_t)(off)) >> 3) & 0x70))

__device__ __forceinline__ uint32_t pack_bf2(float a, float b) {
  __nv_bfloat162 h = __floats2bfloat162_rn(a, b);
  return *(uint32_t*)&h;
}

// ---------------------------------------------------------------------------
// C[M,1024] = A[M,1024] @ W[1024,1024]^T via mma.sync bf16x3.
// grid=(8, M/128), 256 threads (8 warps: 4 along M x 2 along N).
// smem tiles (bf16, 128B rows, SW128): Ahi, Alo, Bhi, Blo (16KB each).
// ---------------------------------------------------------------------------
namespace goff {
constexpr int AHI = 0, ALO = 16384, BHI = 32768, BLO = 49152, TOTAL = 65536;
}

__global__ __launch_bounds__(256) void gemm_mma_kernel(
    const float* __restrict__ A, const float* __restrict__ W,
    float* __restrict__ C) {
  using namespace cfg;
  extern __shared__ char smem[];
  const uint32_t sb = smem_u32(smem);
  const int tid = threadIdx.x;
  const int wid = tid >> 5, lane = tid & 31;
  const int wm = wid & 3;        // warp row group (32 rows)
  const int wn = wid >> 2;       // warp col group (64 cols)
  const int bm = blockIdx.y << 7;
  const int bn = blockIdx.x << 7;

  // gmem load mapping: 4 threads per row, each 16 floats (4 float4).
  const int lrow = tid >> 2;           // 0..63 (two row-iters: +0, +64)
  const int lk = (tid & 3) << 4;       // 0,16,32,48 float offset

  const float* Ap = A + (size_t)(bm + lrow) * D + lk;
  const float* Wp = W + (size_t)(bn + lrow) * D + lk;

  // smem store offsets (bytes) for this thread's two 16B chunks per row-iter.
  // row stride 128B; float k -> 2 bytes.
  const uint32_t st0 = (uint32_t)lrow * 128 + (uint32_t)lk * 2;

  // ldmatrix lane address pieces.
  const int l7 = lane & 7;
  // A: lanes 0-7 rows+0 kLo | 8-15 rows+8 kLo | 16-23 rows+0 kHi | 24-31 rows+8 kHi
  const uint32_t a_row_off = (uint32_t)(wm * 32 + l7 + ((lane >> 3) & 1) * 8) * 128;
  const uint32_t a_col_off = (uint32_t)((lane >> 4) * 16);
  // B: lanes 0-7 rows+0 kLo | 8-15 rows+0 kHi | 16-23 rows+8 kLo | 24-31 rows+8 kHi
  const uint32_t b_row_off = (uint32_t)(wn * 64 + l7 + ((lane >> 4) & 1) * 8) * 128;
  const uint32_t b_col_off = (uint32_t)(((lane >> 3) & 1) * 16);

  float acc[2][8][4];
#pragma unroll
  for (int mt = 0; mt < 2; ++mt)
#pragma unroll
    for (int nt = 0; nt < 8; ++nt)
#pragma unroll
      for (int q = 0; q < 4; ++q) acc[mt][nt][q] = 0.0f;

  for (int ch = 0; ch < 16; ++ch) {
    const int k0 = ch << 6;

    // Load gmem into regs first (overlaps with prior chunk's tail).
    float4 av[2][4], wv[2][4];
#pragma unroll
    for (int ri = 0; ri < 2; ++ri) {
      const float* ap = Ap + (size_t)ri * 64 * D + k0;
      const float* wp = Wp + (size_t)ri * 64 * D + k0;
#pragma unroll
      for (int i = 0; i < 4; ++i) {
        av[ri][i] = *(const float4*)(ap + i * 4);
        wv[ri][i] = *(const float4*)(wp + i * 4);
      }
    }

    __syncthreads();  // prior chunk's ldmatrix readers are done

    // Convert + store hi/lo tiles.
#pragma unroll
    for (int ri = 0; ri < 2; ++ri) {
      const uint32_t so = st0 + (uint32_t)ri * 64 * 128;
#pragma unroll
      for (int half = 0; half < 2; ++half) {  // 2 x 16B chunks (8 floats each)
        float4 v0a = av[ri][half * 2], v1a = av[ri][half * 2 + 1];
        float4 v0w = wv[ri][half * 2], v1w = wv[ri][half * 2 + 1];
        uint32_t off = SW128(so + half * 16);

        uint4 hi_a, lo_a, hi_w, lo_w;
        hi_a.x = pack_bf2(v0a.x, v0a.y); hi_a.y = pack_bf2(v0a.z, v0a.w);
        hi_a.z = pack_bf2(v1a.x, v1a.y); hi_a.w = pack_bf2(v1a.z, v1a.w);
        {
          __nv_bfloat162* h = (__nv_bfloat162*)&hi_a;
          lo_a.x = pack_bf2(v0a.x - __bfloat162float(h[0].x),
                            v0a.y - __bfloat162float(h[0].y));
          lo_a.y = pack_bf2(v0a.z - __bfloat162float(h[1].x),
                            v0a.w - __bfloat162float(h[1].y));
          lo_a.z = pack_bf2(v1a.x - __bfloat162float(h[2].x),
                            v1a.y - __bfloat162float(h[2].y));
          lo_a.w = pack_bf2(v1a.z - __bfloat162float(h[3].x),
                            v1a.w - __bfloat162float(h[3].y));
        }
        hi_w.x = pack_bf2(v0w.x, v0w.y); hi_w.y = pack_bf2(v0w.z, v0w.w);
        hi_w.z = pack_bf2(v1w.x, v1w.y); hi_w.w = pack_bf2(v1w.z, v1w.w);
        {
          __nv_bfloat162* h = (__nv_bfloat162*)&hi_w;
          lo_w.x = pack_bf2(v0w.x - __bfloat162float(h[0].x),
                            v0w.y - __bfloat162float(h[0].y));
          lo_w.y = pack_bf2(v0w.z - __bfloat162float(h[1].x),
                            v0w.w - __bfloat162float(h[1].y));
          lo_w.z = pack_bf2(v1w.x - __bfloat162float(h[2].x),
                            v1w.y - __bfloat162float(h[2].y));
          lo_w.w = pack_bf2(v1w.z - __bfloat162float(h[3].x),
                            v1w.w - __bfloat162float(h[3].y));
        }
        *(uint4*)(smem + goff::AHI + off) = hi_a;
        *(uint4*)(smem + goff::ALO + off) = lo_a;
        *(uint4*)(smem + goff::BHI + off) = hi_w;
        *(uint4*)(smem + goff::BLO + off) = lo_w;
      }
    }
    __syncthreads();

    // Compute: 4 k16 steps x 3 passes.
#pragma unroll
    for (int ks = 0; ks < 4; ++ks) {
      const uint32_t kc = (uint32_t)ks * 32;
      uint32_t ah[2][4], al[2][4], bh[4][4], bl[4][4];
#pragma unroll
      for (int mt = 0; mt < 2; ++mt) {
        uint32_t o = a_row_off + (uint32_t)mt * 16 * 128 + kc + a_col_off;
        uint32_t sw = SW128(o);
        ldm_x4(ah[mt][0], ah[mt][1], ah[mt][2], ah[mt][3], sb + goff::AHI + sw);
        ldm_x4(al[mt][0], al[mt][1], al[mt][2], al[mt][3], sb + goff::ALO + sw);
      }
#pragma unroll
      for (int p = 0; p < 4; ++p) {
        uint32_t o = b_row_off + (uint32_t)p * 16 * 128 + kc + b_col_off;
        uint32_t sw = SW128(o);
        ldm_x4(bh[p][0], bh[p][1], bh[p][2], bh[p][3], sb + goff::BHI + sw);
        ldm_x4(bl[p][0], bl[p][1], bl[p][2], bl[p][3], sb + goff::BLO + sw);
      }
#pragma unroll
      for (int mt = 0; mt < 2; ++mt)
#pragma unroll
        for (int nt = 0; nt < 8; ++nt) {
          const uint32_t* bhp = &bh[nt >> 1][(nt & 1) * 2];
          const uint32_t* blp = &bl[nt >> 1][(nt & 1) * 2];
          mma_bf16(acc[mt][nt], ah[mt], bhp);
          mma_bf16(acc[mt][nt], ah[mt], blp);
          mma_bf16(acc[mt][nt], al[mt], bhp);
        }
    }
  }

  // Epilogue: fragment layout c0,c1 -> (row t/4, col 2(t%4)); c2,c3 -> row+8.
  const int erow = bm + wm * 32 + (lane >> 2);
  const int ecol = bn + wn * 64 + (lane & 3) * 2;
#pragma unroll
  for (int mt = 0; mt < 2; ++mt) {
#pragma unroll
    for (int nt = 0; nt < 8; ++nt) {
      float* c = acc[mt][nt];
      float* p0 = C + (size_t)(erow + mt * 16) * D + ecol + nt * 8;
      *(float2*)p0 = make_float2(c[0], c[1]);
      *(float2*)(p0 + 8 * D) = make_float2(c[2], c[3]);
    }
  }
}

// ---------------------------------------------------------------------------
// Flash attention (fp32 SIMT, unchanged from R0).
// ---------------------------------------------------------------------------
__global__ __launch_bounds__(256) void attn_kernel(
    const float* __restrict__ attn_mask, const int* __restrict__ kpm) {
  using namespace cfg;
  extern __shared__ float sm[];
  float* Qs = sm;
  float* Ks = sm + 64 * SMS;
  float* Vs = sm + 2 * 64 * SMS;
  float* Ps = sm + 3 * 64 * SMS;
  int* kpm_s = (int*)(sm + 4 * 64 * SMS);

  const int tid = threadIdx.x;
  const int qt = blockIdx.x;
  const int h = blockIdx.y;
  const int b = blockIdx.z;
  const int r0 = (tid >> 4) << 2;
  const int c0 = (tid & 15) << 2;

  const float* Qg = g_Q + (size_t)(b * L + qt * 64) * D + h * DH;
  const float* Kg = g_K + (size_t)b * L * D + h * DH;
  const float* Vg = g_V + (size_t)b * L * D + h * DH;

#pragma unroll
  for (int t = 0; t < 4; ++t) {
    int idx = tid + t * 256;
    int row = idx >> 4;
    int d = (idx & 15) << 2;
    float4 q4 = *(const float4*)(Qg + (size_t)row * D + d);
    Qs[(d + 0) * SMS + row] = q4.x;
    Qs[(d + 1) * SMS + row] = q4.y;
    Qs[(d + 2) * SMS + row] = q4.z;
    Qs[(d + 3) * SMS + row] = q4.w;
  }

  float mrun[4], lrun[4], O[4][4];
#pragma unroll
  for (int i = 0; i < 4; ++i) {
    mrun[i] = -1e30f;
    lrun[i] = 0.0f;
#pragma unroll
    for (int q = 0; q < 4; ++q) O[i][q] = 0.0f;
  }

  const float scale = 0.03125f;

  for (int kt = 0; kt < 32; ++kt) {
    __syncthreads();
#pragma unroll
    for (int t = 0; t < 4; ++t) {
      int idx = tid + t * 256;
      int row = idx >> 4;
      int d = (idx & 15) << 2;
      float4 k4 = *(const float4*)(Kg + (size_t)(kt * 64 + row) * D + d);
      Ks[(d + 0) * SMS + row] = k4.x;
      Ks[(d + 1) * SMS + row] = k4.y;
      Ks[(d + 2) * SMS + row] = k4.z;
      Ks[(d + 3) * SMS + row] = k4.w;
      float4 v4 = *(const float4*)(Vg + (size_t)(kt * 64 + row) * D + d);
      *(float4*)(Vs + row * SMS + d) = v4;
    }
    if (tid < 64) kpm_s[tid] = kpm[b * L + kt * 64 + tid];
    __syncthreads();

    float s[4][4] = {};
#pragma unroll 16
    for (int d = 0; d < 64; ++d) {
      float4 aq = *(const float4*)(Qs + d * SMS + r0);
      float4 kq = *(const float4*)(Ks + d * SMS + c0);
      float av[4] = {aq.x, aq.y, aq.z, aq.w};
      float kv[4] = {kq.x, kq.y, kq.z, kq.w};
#pragma unroll
      for (int i = 0; i < 4; ++i)
#pragma unroll
        for (int j = 0; j < 4; ++j)
          s[i][j] = fmaf(av[i], kv[j], s[i][j]);
    }

    const int rowg = qt * 64 + r0;
    const int colg = kt * 64 + c0;
    bool pad[4];
#pragma unroll
    for (int j = 0; j < 4; ++j) pad[j] = (kpm_s[c0 + j] == 0);

#pragma unroll
    for (int i = 0; i < 4; ++i) {
      const float* mrow = attn_mask + (size_t)(rowg + i) * L + colg;
      float sv[4];
#pragma unroll
      for (int j = 0; j < 4; ++j)
        sv[j] = pad[j] ? -1e7f : fmaf(s[i][j], scale, mrow[j]);

      float mx = fmaxf(fmaxf(sv[0], sv[1]), fmaxf(sv[2], sv[3]));
#pragma unroll
      for (int off = 8; off >= 1; off >>= 1)
        mx = fmaxf(mx, __shfl_xor_sync(0xffffffffu, mx, off));

      float mnew = fmaxf(mrun[i], mx);
      float alpha = __expf(mrun[i] - mnew);
      float psum = 0.0f;
#pragma unroll
      for (int j = 0; j < 4; ++j) {
        float p = __expf(sv[j] - mnew);
        psum += p;
        Ps[(c0 + j) * SMS + r0 + i] = p;
      }
#pragma unroll
      for (int off = 8; off >= 1; off >>= 1)
        psum += __shfl_xor_sync(0xffffffffu, psum, off);

      lrun[i] = lrun[i] * alpha + psum;
      mrun[i] = mnew;
#pragma unroll
      for (int q = 0; q < 4; ++q) O[i][q] *= alpha;
    }
    __syncthreads();

#pragma unroll 16
    for (int j = 0; j < 64; ++j) {
      float4 p4 = *(const float4*)(Ps + j * SMS + r0);
      float4 v4 = *(const float4*)(Vs + j * SMS + c0);
      float pv[4] = {p4.x, p4.y, p4.z, p4.w};
      float vv[4] = {v4.x, v4.y, v4.z, v4.w};
#pragma unroll
      for (int i = 0; i < 4; ++i)
#pragma unroll
        for (int q = 0; q < 4; ++q)
          O[i][q] = fmaf(pv[i], vv[q], O[i][q]);
    }
  }

  float* Og = g_A + (size_t)(b * L + qt * 64) * D + h * DH;
#pragma unroll
  for (int i = 0; i < 4; ++i) {
    float inv = 1.0f / lrun[i];
    float4 o = make_float4(O[i][0] * inv, O[i][1] * inv,
                           O[i][2] * inv, O[i][3] * inv);
    *(float4*)(Og + (size_t)(r0 + i) * D + c0) = o;
  }
}

// ---------------------------------------------------------------------------
extern "C" void kernel_launch(void* const* d_in, const int* in_sizes, int n_in,
                              void* d_out, int out_size) {
  using namespace cfg;
  (void)in_sizes; (void)n_in; (void)out_size;

  const float* query = (const float*)d_in[0];
  const float* key   = (const float*)d_in[1];
  const float* value = (const float*)d_in[2];
  const int* kpm     = (const int*)d_in[3];
  const float* mask  = (const float*)d_in[4];
  const float* Wq    = (const float*)d_in[5];
  const float* Wk    = (const float*)d_in[6];
  const float* Wv    = (const float*)d_in[7];
  const float* Wo    = (const float*)d_in[8];
  float* out = (float*)d_out;

  float *Qp, *Kp, *Vp, *Ap;
  cudaGetSymbolAddress((void**)&Qp, g_Q);
  cudaGetSymbolAddress((void**)&Kp, g_K);
  cudaGetSymbolAddress((void**)&Vp, g_V);
  cudaGetSymbolAddress((void**)&Ap, g_A);

  cudaFuncSetAttribute(gemm_mma_kernel,
                       cudaFuncAttributeMaxDynamicSharedMemorySize, goff::TOTAL);

  dim3 gg(D / 128, M / 128);  // (8, 32)
  gemm_mma_kernel<<<gg, 256, goff::TOTAL>>>(query, Wq, Qp);
  gemm_mma_kernel<<<gg, 256, goff::TOTAL>>>(key,   Wk, Kp);
  gemm_mma_kernel<<<gg, 256, goff::TOTAL>>>(value, Wv, Vp);

  const int smem = 4 * 64 * cfg::SMS * (int)sizeof(float) + 64 * (int)sizeof(int);
  cudaFuncSetAttribute(attn_kernel,
                       cudaFuncAttributeMaxDynamicSharedMemorySize, smem);
  attn_kernel<<<dim3(L / 64, H, B), 256, smem>>>(mask, kpm);

  gemm_mma_kernel<<<gg, 256, goff::TOTAL>>>(Ap, Wo, out);
}

// round 4
// speedup vs baseline: 2.2894x; 1.5939x over previous
#include <cuda_runtime.h>
#include <cuda_bf16.h>
#include <cstdint>

// ---------------------------------------------------------------------------
// MHA: B=2, L=2048, D=1024, H=16, dh=64.
// R3: attention converted to mma.sync bf16x3 flash (warp-local softmax,
//     P kept in registers, V transposed at store). GEMMs unchanged from R2.
// ---------------------------------------------------------------------------

namespace cfg {
constexpr int B = 2;
constexpr int L = 2048;
constexpr int D = 1024;
constexpr int H = 16;
constexpr int DH = 64;
constexpr int M = B * L;       // 4096
}

__device__ float g_Q[(size_t)cfg::B * cfg::L * cfg::D];
__device__ float g_K[(size_t)cfg::B * cfg::L * cfg::D];
__device__ float g_V[(size_t)cfg::B * cfg::L * cfg::D];
__device__ float g_A[(size_t)cfg::B * cfg::L * cfg::D];

// ======================= portable tensor-core helpers ======================
__device__ __forceinline__ uint32_t smem_u32(const void* p) {
  uint32_t a;
  asm("{ .reg .u64 t; cvta.to.shared.u64 t, %1; cvt.u32.u64 %0, t; }"
      : "=r"(a) : "l"(p));
  return a;
}

__device__ __forceinline__ void ldm_x4(uint32_t& r0, uint32_t& r1,
                                       uint32_t& r2, uint32_t& r3,
                                       uint32_t addr) {
  asm volatile("ldmatrix.sync.aligned.m8n8.x4.shared.b16 {%0,%1,%2,%3}, [%4];"
               : "=r"(r0), "=r"(r1), "=r"(r2), "=r"(r3) : "r"(addr));
}

__device__ __forceinline__ void mma_bf16(float* c, const uint32_t* a,
                                         const uint32_t* b) {
  asm volatile(
      "mma.sync.aligned.m16n8k16.row.col.f32.bf16.bf16.f32 "
      "{%0,%1,%2,%3}, {%4,%5,%6,%7}, {%8,%9}, {%0,%1,%2,%3};"
      : "+f"(c[0]), "+f"(c[1]), "+f"(c[2]), "+f"(c[3])
      : "r"(a[0]), "r"(a[1]), "r"(a[2]), "r"(a[3]), "r"(b[0]), "r"(b[1]));
}

#define SW128(off) ((off) ^ ((((uint32_t)(off)) >> 3) & 0x70))

__device__ __forceinline__ uint32_t pack_bf2(float a, float b) {
  __nv_bfloat162 h = __floats2bfloat162_rn(a, b);
  return *(uint32_t*)&h;
}
// hi = bf16(a),bf16(b); lo = residuals
__device__ __forceinline__ void pack_hl(float a, float b, uint32_t& hi,
                                        uint32_t& lo) {
  __nv_bfloat162 h = __floats2bfloat162_rn(a, b);
  hi = *(uint32_t*)&h;
  lo = pack_bf2(a - __bfloat162float(h.x), b - __bfloat162float(h.y));
}

// ---------------------------------------------------------------------------
// Projection GEMM (unchanged from R2): C[M,1024] = A @ W^T, mma.sync bf16x3.
// ---------------------------------------------------------------------------
namespace goff {
constexpr int AHI = 0, ALO = 16384, BHI = 32768, BLO = 49152, TOTAL = 65536;
}

__global__ __launch_bounds__(256) void gemm_mma_kernel(
    const float* __restrict__ A, const float* __restrict__ W,
    float* __restrict__ C) {
  using namespace cfg;
  extern __shared__ char smem[];
  const uint32_t sb = smem_u32(smem);
  const int tid = threadIdx.x;
  const int wid = tid >> 5, lane = tid & 31;
  const int wm = wid & 3;
  const int wn = wid >> 2;
  const int bm = blockIdx.y << 7;
  const int bn = blockIdx.x << 7;

  const int lrow = tid >> 2;
  const int lk = (tid & 3) << 4;

  const float* Ap = A + (size_t)(bm + lrow) * D + lk;
  const float* Wp = W + (size_t)(bn + lrow) * D + lk;

  const uint32_t st0 = (uint32_t)lrow * 128 + (uint32_t)lk * 2;

  const int l7 = lane & 7;
  const uint32_t a_row_off = (uint32_t)(wm * 32 + l7 + ((lane >> 3) & 1) * 8) * 128;
  const uint32_t a_col_off = (uint32_t)((lane >> 4) * 16);
  const uint32_t b_row_off = (uint32_t)(wn * 64 + l7 + ((lane >> 4) & 1) * 8) * 128;
  const uint32_t b_col_off = (uint32_t)(((lane >> 3) & 1) * 16);

  float acc[2][8][4];
#pragma unroll
  for (int mt = 0; mt < 2; ++mt)
#pragma unroll
    for (int nt = 0; nt < 8; ++nt)
#pragma unroll
      for (int q = 0; q < 4; ++q) acc[mt][nt][q] = 0.0f;

  for (int ch = 0; ch < 16; ++ch) {
    const int k0 = ch << 6;

    float4 av[2][4], wv[2][4];
#pragma unroll
    for (int ri = 0; ri < 2; ++ri) {
      const float* ap = Ap + (size_t)ri * 64 * D + k0;
      const float* wp = Wp + (size_t)ri * 64 * D + k0;
#pragma unroll
      for (int i = 0; i < 4; ++i) {
        av[ri][i] = *(const float4*)(ap + i * 4);
        wv[ri][i] = *(const float4*)(wp + i * 4);
      }
    }

    __syncthreads();

#pragma unroll
    for (int ri = 0; ri < 2; ++ri) {
      const uint32_t so = st0 + (uint32_t)ri * 64 * 128;
#pragma unroll
      for (int half = 0; half < 2; ++half) {
        float4 v0a = av[ri][half * 2], v1a = av[ri][half * 2 + 1];
        float4 v0w = wv[ri][half * 2], v1w = wv[ri][half * 2 + 1];
        uint32_t off = SW128(so + half * 16);

        uint4 hi_a, lo_a, hi_w, lo_w;
        pack_hl(v0a.x, v0a.y, hi_a.x, lo_a.x);
        pack_hl(v0a.z, v0a.w, hi_a.y, lo_a.y);
        pack_hl(v1a.x, v1a.y, hi_a.z, lo_a.z);
        pack_hl(v1a.z, v1a.w, hi_a.w, lo_a.w);
        pack_hl(v0w.x, v0w.y, hi_w.x, lo_w.x);
        pack_hl(v0w.z, v0w.w, hi_w.y, lo_w.y);
        pack_hl(v1w.x, v1w.y, hi_w.z, lo_w.z);
        pack_hl(v1w.z, v1w.w, hi_w.w, lo_w.w);
        *(uint4*)(smem + goff::AHI + off) = hi_a;
        *(uint4*)(smem + goff::ALO + off) = lo_a;
        *(uint4*)(smem + goff::BHI + off) = hi_w;
        *(uint4*)(smem + goff::BLO + off) = lo_w;
      }
    }
    __syncthreads();

#pragma unroll
    for (int ks = 0; ks < 4; ++ks) {
      const uint32_t kc = (uint32_t)ks * 32;
      uint32_t ah[2][4], al[2][4], bh[4][4], bl[4][4];
#pragma unroll
      for (int mt = 0; mt < 2; ++mt) {
        uint32_t o = a_row_off + (uint32_t)mt * 16 * 128 + kc + a_col_off;
        uint32_t sw = SW128(o);
        ldm_x4(ah[mt][0], ah[mt][1], ah[mt][2], ah[mt][3], sb + goff::AHI + sw);
        ldm_x4(al[mt][0], al[mt][1], al[mt][2], al[mt][3], sb + goff::ALO + sw);
      }
#pragma unroll
      for (int p = 0; p < 4; ++p) {
        uint32_t o = b_row_off + (uint32_t)p * 16 * 128 + kc + b_col_off;
        uint32_t sw = SW128(o);
        ldm_x4(bh[p][0], bh[p][1], bh[p][2], bh[p][3], sb + goff::BHI + sw);
        ldm_x4(bl[p][0], bl[p][1], bl[p][2], bl[p][3], sb + goff::BLO + sw);
      }
#pragma unroll
      for (int mt = 0; mt < 2; ++mt)
#pragma unroll
        for (int nt = 0; nt < 8; ++nt) {
          const uint32_t* bhp = &bh[nt >> 1][(nt & 1) * 2];
          const uint32_t* blp = &bl[nt >> 1][(nt & 1) * 2];
          mma_bf16(acc[mt][nt], ah[mt], bhp);
          mma_bf16(acc[mt][nt], ah[mt], blp);
          mma_bf16(acc[mt][nt], al[mt], bhp);
        }
    }
  }

  const int erow = bm + wm * 32 + (lane >> 2);
  const int ecol = bn + wn * 64 + (lane & 3) * 2;
#pragma unroll
  for (int mt = 0; mt < 2; ++mt) {
#pragma unroll
    for (int nt = 0; nt < 8; ++nt) {
      float* c = acc[mt][nt];
      float* p0 = C + (size_t)(erow + mt * 16) * D + ecol + nt * 8;
      *(float2*)p0 = make_float2(c[0], c[1]);
      *(float2*)(p0 + 8 * D) = make_float2(c[2], c[3]);
    }
  }
}

// ---------------------------------------------------------------------------
// Flash attention on mma.sync bf16x3.
// grid=(16,16,2): 128 q-rows per CTA, 8 warps (warp = 16 rows), k-tiles of 64.
// smem: Qhi/Qlo [128x64], Khi/Klo [64x64], Vthi/Vtlo [64(dh) x 64(key)], kpm.
// ---------------------------------------------------------------------------
namespace aoff {
constexpr int QHI = 0, QLO = 16384, KHI = 32768, KLO = 40960,
              VHI = 49152, VLO = 57344, KPM = 65536, TOTAL = 65536 + 256;
}

__global__ __launch_bounds__(256) void attn_mma_kernel(
    const float* __restrict__ attn_mask, const int* __restrict__ kpm) {
  using namespace cfg;
  extern __shared__ char smem[];
  const uint32_t sb = smem_u32(smem);
  int* kpm_s = (int*)(smem + aoff::KPM);
  const int tid = threadIdx.x;
  const int w = tid >> 5, lane = tid & 31;
  const int qt = blockIdx.x, h = blockIdx.y, b = blockIdx.z;

  const float* Qg = g_Q + (size_t)(b * L + qt * 128) * D + h * DH;
  const float* Kg = g_K + (size_t)b * L * D + h * DH;
  const float* Vg = g_V + (size_t)b * L * D + h * DH;

  // ---- Q tile (128 x 64) -> hi/lo bf16 smem, 128B rows, SW128 ----
  {
    const int lrow = tid >> 2, lcol = (tid & 3) << 4;
#pragma unroll
    for (int ri = 0; ri < 2; ++ri) {
      const int row = lrow + ri * 64;
      const float* qp = Qg + (size_t)row * D + lcol;
#pragma unroll
      for (int cc = 0; cc < 2; ++cc) {
        float4 v0 = *(const float4*)(qp + cc * 8);
        float4 v1 = *(const float4*)(qp + cc * 8 + 4);
        uint4 hi, lo;
        pack_hl(v0.x, v0.y, hi.x, lo.x);
        pack_hl(v0.z, v0.w, hi.y, lo.y);
        pack_hl(v1.x, v1.y, hi.z, lo.z);
        pack_hl(v1.z, v1.w, hi.w, lo.w);
        uint32_t off = SW128((uint32_t)row * 128 + (uint32_t)lcol * 2 + cc * 16);
        *(uint4*)(smem + aoff::QHI + off) = hi;
        *(uint4*)(smem + aoff::QLO + off) = lo;
      }
    }
  }
  __syncthreads();

  const int l7 = lane & 7;
  const uint32_t a_row = (uint32_t)(w * 16 + (lane & 15));
  const uint32_t a_colb = (uint32_t)((lane >> 4) * 16);
  const uint32_t b_row = (uint32_t)(l7 + ((lane >> 4) & 1) * 8);
  const uint32_t b_colb = (uint32_t)(((lane >> 3) & 1) * 16);

  // Preload Q fragments (loop-invariant): 4 k-steps, hi+lo.
  uint32_t qh[4][4], ql[4][4];
#pragma unroll
  for (int ks = 0; ks < 4; ++ks) {
    uint32_t off = SW128(a_row * 128 + (uint32_t)ks * 32 + a_colb);
    ldm_x4(qh[ks][0], qh[ks][1], qh[ks][2], qh[ks][3], sb + aoff::QHI + off);
    ldm_x4(ql[ks][0], ql[ks][1], ql[ks][2], ql[ks][3], sb + aoff::QLO + off);
  }

  float m0 = -1e30f, m1 = -1e30f, l0 = 0.0f, l1 = 0.0f;
  float O[8][4];
#pragma unroll
  for (int nt = 0; nt < 8; ++nt)
#pragma unroll
    for (int q = 0; q < 4; ++q) O[nt][q] = 0.0f;

  const int r0g = qt * 128 + w * 16 + (lane >> 2);
  const float scale = 0.03125f;  // 1/sqrt(1024)

  for (int kt = 0; kt < 32; ++kt) {
    __syncthreads();  // prior iteration's smem readers done
    // K tile [64 key x 64 dh] hi/lo.
    {
      const int row = tid >> 2, lcol = (tid & 3) << 4;
      const float* kp = Kg + (size_t)(kt * 64 + row) * D + lcol;
#pragma unroll
      for (int cc = 0; cc < 2; ++cc) {
        float4 v0 = *(const float4*)(kp + cc * 8);
        float4 v1 = *(const float4*)(kp + cc * 8 + 4);
        uint4 hi, lo;
        pack_hl(v0.x, v0.y, hi.x, lo.x);
        pack_hl(v0.z, v0.w, hi.y, lo.y);
        pack_hl(v1.x, v1.y, hi.z, lo.z);
        pack_hl(v1.z, v1.w, hi.w, lo.w);
        uint32_t off = SW128((uint32_t)row * 128 + (uint32_t)lcol * 2 + cc * 16);
        *(uint4*)(smem + aoff::KHI + off) = hi;
        *(uint4*)(smem + aoff::KLO + off) = lo;
      }
      // V tile transposed -> Vt[dh][key], hi/lo. Thread: 4 keys x 4 dh block.
      const int db = (tid & 15) << 2, kb = (tid >> 4) << 2;
      float vv[4][4];
#pragma unroll
      for (int i = 0; i < 4; ++i)
        *(float4*)vv[i] = *(const float4*)(Vg + (size_t)(kt * 64 + kb + i) * D + db);
#pragma unroll
      for (int j = 0; j < 4; ++j) {
        uint2 hi, lo;
        pack_hl(vv[0][j], vv[1][j], hi.x, lo.x);
        pack_hl(vv[2][j], vv[3][j], hi.y, lo.y);
        uint32_t off = SW128((uint32_t)(db + j) * 128 + (uint32_t)kb * 2);
        *(uint2*)(smem + aoff::VHI + off) = hi;
        *(uint2*)(smem + aoff::VLO + off) = lo;
      }
      if (tid < 64) kpm_s[tid] = kpm[b * L + kt * 64 + tid];
    }
    __syncthreads();

    // Mask preload (additive mask tile).
    float2 mv0[8], mv1[8];
    {
      const int colg = kt * 64 + 2 * (lane & 3);
      const float* mrow0 = attn_mask + (size_t)r0g * L + colg;
      const float* mrow1 = attn_mask + (size_t)(r0g + 8) * L + colg;
#pragma unroll
      for (int nt = 0; nt < 8; ++nt) {
        mv0[nt] = *(const float2*)(mrow0 + nt * 8);
        mv1[nt] = *(const float2*)(mrow1 + nt * 8);
      }
    }

    // S = Q K^T (3-pass hi/lo).
    float S[8][4];
#pragma unroll
    for (int nt = 0; nt < 8; ++nt)
#pragma unroll
      for (int q = 0; q < 4; ++q) S[nt][q] = 0.0f;

#pragma unroll
    for (int ks = 0; ks < 4; ++ks) {
      uint32_t kh[4][4], kl[4][4];
#pragma unroll
      for (int p = 0; p < 4; ++p) {
        uint32_t off = SW128(((uint32_t)p * 16 + b_row) * 128 + (uint32_t)ks * 32 + b_colb);
        ldm_x4(kh[p][0], kh[p][1], kh[p][2], kh[p][3], sb + aoff::KHI + off);
        ldm_x4(kl[p][0], kl[p][1], kl[p][2], kl[p][3], sb + aoff::KLO + off);
      }
#pragma unroll
      for (int nt = 0; nt < 8; ++nt) {
        const uint32_t* bh = &kh[nt >> 1][(nt & 1) * 2];
        const uint32_t* bl = &kl[nt >> 1][(nt & 1) * 2];
        mma_bf16(S[nt], qh[ks], bh);
        mma_bf16(S[nt], qh[ks], bl);
        mma_bf16(S[nt], ql[ks], bh);
      }
    }

    // Epilogue: scale + mask + padding, online softmax (warp-local, quad shfl).
    float tmax0 = -1e30f, tmax1 = -1e30f;
#pragma unroll
    for (int nt = 0; nt < 8; ++nt) {
      const int c = nt * 8 + 2 * (lane & 3);
      const bool p0 = (kpm_s[c] == 0), p1 = (kpm_s[c + 1] == 0);
      float sv0 = p0 ? -1e7f : fmaf(S[nt][0], scale, mv0[nt].x);
      float sv1 = p1 ? -1e7f : fmaf(S[nt][1], scale, mv0[nt].y);
      float sv2 = p0 ? -1e7f : fmaf(S[nt][2], scale, mv1[nt].x);
      float sv3 = p1 ? -1e7f : fmaf(S[nt][3], scale, mv1[nt].y);
      S[nt][0] = sv0; S[nt][1] = sv1; S[nt][2] = sv2; S[nt][3] = sv3;
      tmax0 = fmaxf(tmax0, fmaxf(sv0, sv1));
      tmax1 = fmaxf(tmax1, fmaxf(sv2, sv3));
    }
    tmax0 = fmaxf(tmax0, __shfl_xor_sync(0xffffffffu, tmax0, 1));
    tmax0 = fmaxf(tmax0, __shfl_xor_sync(0xffffffffu, tmax0, 2));
    tmax1 = fmaxf(tmax1, __shfl_xor_sync(0xffffffffu, tmax1, 1));
    tmax1 = fmaxf(tmax1, __shfl_xor_sync(0xffffffffu, tmax1, 2));

    const float mn0 = fmaxf(m0, tmax0), mn1 = fmaxf(m1, tmax1);
    const float alpha0 = __expf(m0 - mn0), alpha1 = __expf(m1 - mn1);
    float rs0 = 0.0f, rs1 = 0.0f;
#pragma unroll
    for (int nt = 0; nt < 8; ++nt) {
      float p0 = __expf(S[nt][0] - mn0);
      float p1 = __expf(S[nt][1] - mn0);
      float p2 = __expf(S[nt][2] - mn1);
      float p3 = __expf(S[nt][3] - mn1);
      S[nt][0] = p0; S[nt][1] = p1; S[nt][2] = p2; S[nt][3] = p3;
      rs0 += p0 + p1;
      rs1 += p2 + p3;
      O[nt][0] *= alpha0; O[nt][1] *= alpha0;
      O[nt][2] *= alpha1; O[nt][3] *= alpha1;
    }
    rs0 += __shfl_xor_sync(0xffffffffu, rs0, 1);
    rs0 += __shfl_xor_sync(0xffffffffu, rs0, 2);
    rs1 += __shfl_xor_sync(0xffffffffu, rs1, 1);
    rs1 += __shfl_xor_sync(0xffffffffu, rs1, 2);
    l0 = l0 * alpha0 + rs0; m0 = mn0;
    l1 = l1 * alpha1 + rs1; m1 = mn1;

    // O += P V  (P from registers; B from Vt with the verified non-trans path)
#pragma unroll
    for (int t = 0; t < 4; ++t) {
      uint32_t ah[4], al[4];
      pack_hl(S[2 * t][0], S[2 * t][1], ah[0], al[0]);
      pack_hl(S[2 * t][2], S[2 * t][3], ah[1], al[1]);
      pack_hl(S[2 * t + 1][0], S[2 * t + 1][1], ah[2], al[2]);
      pack_hl(S[2 * t + 1][2], S[2 * t + 1][3], ah[3], al[3]);
      uint32_t vh[4][4], vl[4][4];
#pragma unroll
      for (int p = 0; p < 4; ++p) {
        uint32_t off = SW128(((uint32_t)p * 16 + b_row) * 128 + (uint32_t)t * 32 + b_colb);
        ldm_x4(vh[p][0], vh[p][1], vh[p][2], vh[p][3], sb + aoff::VHI + off);
        ldm_x4(vl[p][0], vl[p][1], vl[p][2], vl[p][3], sb + aoff::VLO + off);
      }
#pragma unroll
      for (int nt = 0; nt < 8; ++nt) {
        const uint32_t* bh = &vh[nt >> 1][(nt & 1) * 2];
        const uint32_t* bl = &vl[nt >> 1][(nt & 1) * 2];
        mma_bf16(O[nt], ah, bh);
        mma_bf16(O[nt], ah, bl);
        mma_bf16(O[nt], al, bh);
      }
    }
  }

  // Normalize + write to g_A in [b, l, h*dh] layout.
  const float inv0 = 1.0f / l0, inv1 = 1.0f / l1;
  float* Og = g_A + (size_t)(b * L + r0g) * D + h * DH + 2 * (lane & 3);
#pragma unroll
  for (int nt = 0; nt < 8; ++nt) {
    *(float2*)(Og + nt * 8) = make_float2(O[nt][0] * inv0, O[nt][1] * inv0);
    *(float2*)(Og + 8 * D + nt * 8) = make_float2(O[nt][2] * inv1, O[nt][3] * inv1);
  }
}

// ---------------------------------------------------------------------------
extern "C" void kernel_launch(void* const* d_in, const int* in_sizes, int n_in,
                              void* d_out, int out_size) {
  using namespace cfg;
  (void)in_sizes; (void)n_in; (void)out_size;

  const float* query = (const float*)d_in[0];
  const float* key   = (const float*)d_in[1];
  const float* value = (const float*)d_in[2];
  const int* kpm     = (const int*)d_in[3];
  const float* mask  = (const float*)d_in[4];
  const float* Wq    = (const float*)d_in[5];
  const float* Wk    = (const float*)d_in[6];
  const float* Wv    = (const float*)d_in[7];
  const float* Wo    = (const float*)d_in[8];
  float* out = (float*)d_out;

  float *Qp, *Kp, *Vp, *Ap;
  cudaGetSymbolAddress((void**)&Qp, g_Q);
  cudaGetSymbolAddress((void**)&Kp, g_K);
  cudaGetSymbolAddress((void**)&Vp, g_V);
  cudaGetSymbolAddress((void**)&Ap, g_A);

  cudaFuncSetAttribute(gemm_mma_kernel,
                       cudaFuncAttributeMaxDynamicSharedMemorySize, goff::TOTAL);
  cudaFuncSetAttribute(attn_mma_kernel,
                       cudaFuncAttributeMaxDynamicSharedMemorySize, aoff::TOTAL);

  dim3 gg(D / 128, M / 128);  // (8, 32)
  gemm_mma_kernel<<<gg, 256, goff::TOTAL>>>(query, Wq, Qp);
  gemm_mma_kernel<<<gg, 256, goff::TOTAL>>>(key,   Wk, Kp);
  gemm_mma_kernel<<<gg, 256, goff::TOTAL>>>(value, Wv, Vp);

  attn_mma_kernel<<<dim3(L / 128, H, B), 256, aoff::TOTAL>>>(mask, kpm);

  gemm_mma_kernel<<<gg, 256, goff::TOTAL>>>(Ap, Wo, out);
}

// round 5
// speedup vs baseline: 2.3122x; 1.0100x over previous
#include <cuda_runtime.h>
#include <cuda_bf16.h>
#include <cstdint>

// ---------------------------------------------------------------------------
// MHA: B=2, L=2048, D=1024, H=16, dh=64.
// R4: attention CTA halved (64 q-rows, 128 thr, occ 3 CTA/SM) for cross-CTA
//     overlap; log2-domain softmax (ex2.approx, scale folded into Q).
//     GEMMs unchanged (mma.sync bf16x3).
// ---------------------------------------------------------------------------

namespace cfg {
constexpr int B = 2;
constexpr int L = 2048;
constexpr int D = 1024;
constexpr int H = 16;
constexpr int DH = 64;
constexpr int M = B * L;
}

__device__ float g_Q[(size_t)cfg::B * cfg::L * cfg::D];
__device__ float g_K[(size_t)cfg::B * cfg::L * cfg::D];
__device__ float g_V[(size_t)cfg::B * cfg::L * cfg::D];
__device__ float g_A[(size_t)cfg::B * cfg::L * cfg::D];

// ======================= portable tensor-core helpers ======================
__device__ __forceinline__ uint32_t smem_u32(const void* p) {
  uint32_t a;
  asm("{ .reg .u64 t; cvta.to.shared.u64 t, %1; cvt.u32.u64 %0, t; }"
      : "=r"(a) : "l"(p));
  return a;
}

__device__ __forceinline__ void ldm_x4(uint32_t& r0, uint32_t& r1,
                                       uint32_t& r2, uint32_t& r3,
                                       uint32_t addr) {
  asm volatile("ldmatrix.sync.aligned.m8n8.x4.shared.b16 {%0,%1,%2,%3}, [%4];"
               : "=r"(r0), "=r"(r1), "=r"(r2), "=r"(r3) : "r"(addr));
}

__device__ __forceinline__ void mma_bf16(float* c, const uint32_t* a,
                                         const uint32_t* b) {
  asm volatile(
      "mma.sync.aligned.m16n8k16.row.col.f32.bf16.bf16.f32 "
      "{%0,%1,%2,%3}, {%4,%5,%6,%7}, {%8,%9}, {%0,%1,%2,%3};"
      : "+f"(c[0]), "+f"(c[1]), "+f"(c[2]), "+f"(c[3])
      : "r"(a[0]), "r"(a[1]), "r"(a[2]), "r"(a[3]), "r"(b[0]), "r"(b[1]));
}

__device__ __forceinline__ float fast_exp2(float x) {
  float y;
  asm("ex2.approx.f32 %0, %1;" : "=f"(y) : "f"(x));
  return y;
}

#define SW128(off) ((off) ^ ((((uint32_t)(off)) >> 3) & 0x70))

__device__ __forceinline__ uint32_t pack_bf2(float a, float b) {
  __nv_bfloat162 h = __floats2bfloat162_rn(a, b);
  return *(uint32_t*)&h;
}
__device__ __forceinline__ void pack_hl(float a, float b, uint32_t& hi,
                                        uint32_t& lo) {
  __nv_bfloat162 h = __floats2bfloat162_rn(a, b);
  hi = *(uint32_t*)&h;
  lo = pack_bf2(a - __bfloat162float(h.x), b - __bfloat162float(h.y));
}

// ---------------------------------------------------------------------------
// Projection GEMM (unchanged): C[M,1024] = A @ W^T, mma.sync bf16x3.
// ---------------------------------------------------------------------------
namespace goff {
constexpr int AHI = 0, ALO = 16384, BHI = 32768, BLO = 49152, TOTAL = 65536;
}

__global__ __launch_bounds__(256) void gemm_mma_kernel(
    const float* __restrict__ A, const float* __restrict__ W,
    float* __restrict__ C) {
  using namespace cfg;
  extern __shared__ char smem[];
  const uint32_t sb = smem_u32(smem);
  const int tid = threadIdx.x;
  const int wid = tid >> 5, lane = tid & 31;
  const int wm = wid & 3;
  const int wn = wid >> 2;
  const int bm = blockIdx.y << 7;
  const int bn = blockIdx.x << 7;

  const int lrow = tid >> 2;
  const int lk = (tid & 3) << 4;

  const float* Ap = A + (size_t)(bm + lrow) * D + lk;
  const float* Wp = W + (size_t)(bn + lrow) * D + lk;

  const uint32_t st0 = (uint32_t)lrow * 128 + (uint32_t)lk * 2;

  const int l7 = lane & 7;
  const uint32_t a_row_off = (uint32_t)(wm * 32 + l7 + ((lane >> 3) & 1) * 8) * 128;
  const uint32_t a_col_off = (uint32_t)((lane >> 4) * 16);
  const uint32_t b_row_off = (uint32_t)(wn * 64 + l7 + ((lane >> 4) & 1) * 8) * 128;
  const uint32_t b_col_off = (uint32_t)(((lane >> 3) & 1) * 16);

  float acc[2][8][4];
#pragma unroll
  for (int mt = 0; mt < 2; ++mt)
#pragma unroll
    for (int nt = 0; nt < 8; ++nt)
#pragma unroll
      for (int q = 0; q < 4; ++q) acc[mt][nt][q] = 0.0f;

  for (int ch = 0; ch < 16; ++ch) {
    const int k0 = ch << 6;

    float4 av[2][4], wv[2][4];
#pragma unroll
    for (int ri = 0; ri < 2; ++ri) {
      const float* ap = Ap + (size_t)ri * 64 * D + k0;
      const float* wp = Wp + (size_t)ri * 64 * D + k0;
#pragma unroll
      for (int i = 0; i < 4; ++i) {
        av[ri][i] = *(const float4*)(ap + i * 4);
        wv[ri][i] = *(const float4*)(wp + i * 4);
      }
    }

    __syncthreads();

#pragma unroll
    for (int ri = 0; ri < 2; ++ri) {
      const uint32_t so = st0 + (uint32_t)ri * 64 * 128;
#pragma unroll
      for (int half = 0; half < 2; ++half) {
        float4 v0a = av[ri][half * 2], v1a = av[ri][half * 2 + 1];
        float4 v0w = wv[ri][half * 2], v1w = wv[ri][half * 2 + 1];
        uint32_t off = SW128(so + half * 16);

        uint4 hi_a, lo_a, hi_w, lo_w;
        pack_hl(v0a.x, v0a.y, hi_a.x, lo_a.x);
        pack_hl(v0a.z, v0a.w, hi_a.y, lo_a.y);
        pack_hl(v1a.x, v1a.y, hi_a.z, lo_a.z);
        pack_hl(v1a.z, v1a.w, hi_a.w, lo_a.w);
        pack_hl(v0w.x, v0w.y, hi_w.x, lo_w.x);
        pack_hl(v0w.z, v0w.w, hi_w.y, lo_w.y);
        pack_hl(v1w.x, v1w.y, hi_w.z, lo_w.z);
        pack_hl(v1w.z, v1w.w, hi_w.w, lo_w.w);
        *(uint4*)(smem + goff::AHI + off) = hi_a;
        *(uint4*)(smem + goff::ALO + off) = lo_a;
        *(uint4*)(smem + goff::BHI + off) = hi_w;
        *(uint4*)(smem + goff::BLO + off) = lo_w;
      }
    }
    __syncthreads();

#pragma unroll
    for (int ks = 0; ks < 4; ++ks) {
      const uint32_t kc = (uint32_t)ks * 32;
      uint32_t ah[2][4], al[2][4], bh[4][4], bl[4][4];
#pragma unroll
      for (int mt = 0; mt < 2; ++mt) {
        uint32_t o = a_row_off + (uint32_t)mt * 16 * 128 + kc + a_col_off;
        uint32_t sw = SW128(o);
        ldm_x4(ah[mt][0], ah[mt][1], ah[mt][2], ah[mt][3], sb + goff::AHI + sw);
        ldm_x4(al[mt][0], al[mt][1], al[mt][2], al[mt][3], sb + goff::ALO + sw);
      }
#pragma unroll
      for (int p = 0; p < 4; ++p) {
        uint32_t o = b_row_off + (uint32_t)p * 16 * 128 + kc + b_col_off;
        uint32_t sw = SW128(o);
        ldm_x4(bh[p][0], bh[p][1], bh[p][2], bh[p][3], sb + goff::BHI + sw);
        ldm_x4(bl[p][0], bl[p][1], bl[p][2], bl[p][3], sb + goff::BLO + sw);
      }
#pragma unroll
      for (int mt = 0; mt < 2; ++mt)
#pragma unroll
        for (int nt = 0; nt < 8; ++nt) {
          const uint32_t* bhp = &bh[nt >> 1][(nt & 1) * 2];
          const uint32_t* blp = &bl[nt >> 1][(nt & 1) * 2];
          mma_bf16(acc[mt][nt], ah[mt], bhp);
          mma_bf16(acc[mt][nt], ah[mt], blp);
          mma_bf16(acc[mt][nt], al[mt], bhp);
        }
    }
  }

  const int erow = bm + wm * 32 + (lane >> 2);
  const int ecol = bn + wn * 64 + (lane & 3) * 2;
#pragma unroll
  for (int mt = 0; mt < 2; ++mt) {
#pragma unroll
    for (int nt = 0; nt < 8; ++nt) {
      float* c = acc[mt][nt];
      float* p0 = C + (size_t)(erow + mt * 16) * D + ecol + nt * 8;
      *(float2*)p0 = make_float2(c[0], c[1]);
      *(float2*)(p0 + 8 * D) = make_float2(c[2], c[3]);
    }
  }
}

// ---------------------------------------------------------------------------
// Flash attention, mma.sync bf16x3, 64 q-rows / 128 threads / 4 warps.
// smem: Qhi/Qlo [64x64], Khi/Klo [64x64], Vthi/Vtlo [64(dh)x64(key)], kpm.
// Softmax in log2 domain: Q pre-scaled by scale*log2e, mask by log2e.
// ---------------------------------------------------------------------------
namespace aoff {
constexpr int QHI = 0, QLO = 8192, KHI = 16384, KLO = 24576,
              VHI = 32768, VLO = 40960, KPM = 49152, TOTAL = 49152 + 256;
}

__global__ __launch_bounds__(128, 3) void attn_mma_kernel(
    const float* __restrict__ attn_mask, const int* __restrict__ kpm) {
  using namespace cfg;
  extern __shared__ char smem[];
  const uint32_t sb = smem_u32(smem);
  int* kpm_s = (int*)(smem + aoff::KPM);
  const int tid = threadIdx.x;
  const int w = tid >> 5, lane = tid & 31;
  const int qt = blockIdx.x, h = blockIdx.y, b = blockIdx.z;

  const float L2E = 1.44269504088896f;
  const float QSC = 0.03125f * L2E;  // (1/sqrt(1024)) * log2(e)

  const float* Qg = g_Q + (size_t)(b * L + qt * 64) * D + h * DH;
  const float* Kg = g_K + (size_t)b * L * D + h * DH;
  const float* Vg = g_V + (size_t)b * L * D + h * DH;

  // ---- Q tile (64 x 64) -> hi/lo bf16 smem (pre-scaled), 128B rows ----
  {
    const int lrow = tid >> 1, lcol = (tid & 1) << 5;  // 32 floats/thread
    const float* qp = Qg + (size_t)lrow * D + lcol;
#pragma unroll
    for (int cc = 0; cc < 4; ++cc) {  // 4 chunks of 8 floats
      float4 v0 = *(const float4*)(qp + cc * 8);
      float4 v1 = *(const float4*)(qp + cc * 8 + 4);
      uint4 hi, lo;
      pack_hl(v0.x * QSC, v0.y * QSC, hi.x, lo.x);
      pack_hl(v0.z * QSC, v0.w * QSC, hi.y, lo.y);
      pack_hl(v1.x * QSC, v1.y * QSC, hi.z, lo.z);
      pack_hl(v1.z * QSC, v1.w * QSC, hi.w, lo.w);
      uint32_t off = SW128((uint32_t)lrow * 128 + (uint32_t)lcol * 2 + cc * 16);
      *(uint4*)(smem + aoff::QHI + off) = hi;
      *(uint4*)(smem + aoff::QLO + off) = lo;
    }
  }
  __syncthreads();

  const int l7 = lane & 7;
  const uint32_t a_row = (uint32_t)(w * 16 + (lane & 15));
  const uint32_t a_colb = (uint32_t)((lane >> 4) * 16);
  const uint32_t b_row = (uint32_t)(l7 + ((lane >> 4) & 1) * 8);
  const uint32_t b_colb = (uint32_t)(((lane >> 3) & 1) * 16);

  uint32_t qh[4][4], ql[4][4];
#pragma unroll
  for (int ks = 0; ks < 4; ++ks) {
    uint32_t off = SW128(a_row * 128 + (uint32_t)ks * 32 + a_colb);
    ldm_x4(qh[ks][0], qh[ks][1], qh[ks][2], qh[ks][3], sb + aoff::QHI + off);
    ldm_x4(ql[ks][0], ql[ks][1], ql[ks][2], ql[ks][3], sb + aoff::QLO + off);
  }

  float m0 = -1e30f, m1 = -1e30f, l0 = 0.0f, l1 = 0.0f;
  float O[8][4];
#pragma unroll
  for (int nt = 0; nt < 8; ++nt)
#pragma unroll
    for (int q = 0; q < 4; ++q) O[nt][q] = 0.0f;

  const int r0g = qt * 64 + w * 16 + (lane >> 2);

  for (int kt = 0; kt < 32; ++kt) {
    __syncthreads();
    // K tile [64 key x 64 dh] hi/lo.
    {
      const int lrow = tid >> 1, lcol = (tid & 1) << 5;
      const float* kp = Kg + (size_t)(kt * 64 + lrow) * D + lcol;
#pragma unroll
      for (int cc = 0; cc < 4; ++cc) {
        float4 v0 = *(const float4*)(kp + cc * 8);
        float4 v1 = *(const float4*)(kp + cc * 8 + 4);
        uint4 hi, lo;
        pack_hl(v0.x, v0.y, hi.x, lo.x);
        pack_hl(v0.z, v0.w, hi.y, lo.y);
        pack_hl(v1.x, v1.y, hi.z, lo.z);
        pack_hl(v1.z, v1.w, hi.w, lo.w);
        uint32_t off = SW128((uint32_t)lrow * 128 + (uint32_t)lcol * 2 + cc * 16);
        *(uint4*)(smem + aoff::KHI + off) = hi;
        *(uint4*)(smem + aoff::KLO + off) = lo;
      }
      // V tile transposed -> Vt[dh][key]; thread: 8 keys x 4 dh.
      const int db = (tid & 15) << 2, kb = (tid >> 4) << 3;
      float vv[8][4];
#pragma unroll
      for (int i = 0; i < 8; ++i)
        *(float4*)vv[i] = *(const float4*)(Vg + (size_t)(kt * 64 + kb + i) * D + db);
#pragma unroll
      for (int j = 0; j < 4; ++j) {
        uint4 hi, lo;
        pack_hl(vv[0][j], vv[1][j], hi.x, lo.x);
        pack_hl(vv[2][j], vv[3][j], hi.y, lo.y);
        pack_hl(vv[4][j], vv[5][j], hi.z, lo.z);
        pack_hl(vv[6][j], vv[7][j], hi.w, lo.w);
        uint32_t off = SW128((uint32_t)(db + j) * 128 + (uint32_t)kb * 2);
        *(uint4*)(smem + aoff::VHI + off) = hi;
        *(uint4*)(smem + aoff::VLO + off) = lo;
      }
      if (tid < 64) kpm_s[tid] = kpm[b * L + kt * 64 + tid];
    }
    __syncthreads();

    // Mask preload (x log2e).
    float2 mv0[8], mv1[8];
    {
      const int colg = kt * 64 + 2 * (lane & 3);
      const float* mrow0 = attn_mask + (size_t)r0g * L + colg;
      const float* mrow1 = attn_mask + (size_t)(r0g + 8) * L + colg;
#pragma unroll
      for (int nt = 0; nt < 8; ++nt) {
        float2 a = *(const float2*)(mrow0 + nt * 8);
        float2 c = *(const float2*)(mrow1 + nt * 8);
        mv0[nt] = make_float2(a.x * L2E, a.y * L2E);
        mv1[nt] = make_float2(c.x * L2E, c.y * L2E);
      }
    }

    // S = Q K^T (3-pass hi/lo); S already in log2 units (Q pre-scaled).
    float S[8][4];
#pragma unroll
    for (int nt = 0; nt < 8; ++nt)
#pragma unroll
      for (int q = 0; q < 4; ++q) S[nt][q] = 0.0f;

#pragma unroll
    for (int ks = 0; ks < 4; ++ks) {
      uint32_t kh[4][4], kl[4][4];
#pragma unroll
      for (int p = 0; p < 4; ++p) {
        uint32_t off = SW128(((uint32_t)p * 16 + b_row) * 128 + (uint32_t)ks * 32 + b_colb);
        ldm_x4(kh[p][0], kh[p][1], kh[p][2], kh[p][3], sb + aoff::KHI + off);
        ldm_x4(kl[p][0], kl[p][1], kl[p][2], kl[p][3], sb + aoff::KLO + off);
      }
#pragma unroll
      for (int nt = 0; nt < 8; ++nt) {
        const uint32_t* bh = &kh[nt >> 1][(nt & 1) * 2];
        const uint32_t* bl = &kl[nt >> 1][(nt & 1) * 2];
        mma_bf16(S[nt], qh[ks], bh);
        mma_bf16(S[nt], qh[ks], bl);
        mma_bf16(S[nt], ql[ks], bh);
      }
    }

    // mask + padding + online softmax (log2 domain, quad shfl).
    float tmax0 = -1e30f, tmax1 = -1e30f;
#pragma unroll
    for (int nt = 0; nt < 8; ++nt) {
      const int c = nt * 8 + 2 * (lane & 3);
      const bool p0 = (kpm_s[c] == 0), p1 = (kpm_s[c + 1] == 0);
      float sv0 = p0 ? -1e7f : (S[nt][0] + mv0[nt].x);
      float sv1 = p1 ? -1e7f : (S[nt][1] + mv0[nt].y);
      float sv2 = p0 ? -1e7f : (S[nt][2] + mv1[nt].x);
      float sv3 = p1 ? -1e7f : (S[nt][3] + mv1[nt].y);
      S[nt][0] = sv0; S[nt][1] = sv1; S[nt][2] = sv2; S[nt][3] = sv3;
      tmax0 = fmaxf(tmax0, fmaxf(sv0, sv1));
      tmax1 = fmaxf(tmax1, fmaxf(sv2, sv3));
    }
    tmax0 = fmaxf(tmax0, __shfl_xor_sync(0xffffffffu, tmax0, 1));
    tmax0 = fmaxf(tmax0, __shfl_xor_sync(0xffffffffu, tmax0, 2));
    tmax1 = fmaxf(tmax1, __shfl_xor_sync(0xffffffffu, tmax1, 1));
    tmax1 = fmaxf(tmax1, __shfl_xor_sync(0xffffffffu, tmax1, 2));

    const float mn0 = fmaxf(m0, tmax0), mn1 = fmaxf(m1, tmax1);
    const float alpha0 = fast_exp2(m0 - mn0), alpha1 = fast_exp2(m1 - mn1);
    float rs0 = 0.0f, rs1 = 0.0f;
#pragma unroll
    for (int nt = 0; nt < 8; ++nt) {
      float p0 = fast_exp2(S[nt][0] - mn0);
      float p1 = fast_exp2(S[nt][1] - mn0);
      float p2 = fast_exp2(S[nt][2] - mn1);
      float p3 = fast_exp2(S[nt][3] - mn1);
      S[nt][0] = p0; S[nt][1] = p1; S[nt][2] = p2; S[nt][3] = p3;
      rs0 += p0 + p1;
      rs1 += p2 + p3;
      O[nt][0] *= alpha0; O[nt][1] *= alpha0;
      O[nt][2] *= alpha1; O[nt][3] *= alpha1;
    }
    rs0 += __shfl_xor_sync(0xffffffffu, rs0, 1);
    rs0 += __shfl_xor_sync(0xffffffffu, rs0, 2);
    rs1 += __shfl_xor_sync(0xffffffffu, rs1, 1);
    rs1 += __shfl_xor_sync(0xffffffffu, rs1, 2);
    l0 = l0 * alpha0 + rs0; m0 = mn0;
    l1 = l1 * alpha1 + rs1; m1 = mn1;

    // O += P V (P packed from registers).
#pragma unroll
    for (int t = 0; t < 4; ++t) {
      uint32_t ah[4], al[4];
      pack_hl(S[2 * t][0], S[2 * t][1], ah[0], al[0]);
      pack_hl(S[2 * t][2], S[2 * t][3], ah[1], al[1]);
      pack_hl(S[2 * t + 1][0], S[2 * t + 1][1], ah[2], al[2]);
      pack_hl(S[2 * t + 1][2], S[2 * t + 1][3], ah[3], al[3]);
      uint32_t vh[4][4], vl[4][4];
#pragma unroll
      for (int p = 0; p < 4; ++p) {
        uint32_t off = SW128(((uint32_t)p * 16 + b_row) * 128 + (uint32_t)t * 32 + b_colb);
        ldm_x4(vh[p][0], vh[p][1], vh[p][2], vh[p][3], sb + aoff::VHI + off);
        ldm_x4(vl[p][0], vl[p][1], vl[p][2], vl[p][3], sb + aoff::VLO + off);
      }
#pragma unroll
      for (int nt = 0; nt < 8; ++nt) {
        const uint32_t* bh = &vh[nt >> 1][(nt & 1) * 2];
        const uint32_t* bl = &vl[nt >> 1][(nt & 1) * 2];
        mma_bf16(O[nt], ah, bh);
        mma_bf16(O[nt], ah, bl);
        mma_bf16(O[nt], al, bh);
      }
    }
  }

  const float inv0 = 1.0f / l0, inv1 = 1.0f / l1;
  float* Og = g_A + (size_t)(b * L + r0g) * D + h * DH + 2 * (lane & 3);
#pragma unroll
  for (int nt = 0; nt < 8; ++nt) {
    *(float2*)(Og + nt * 8) = make_float2(O[nt][0] * inv0, O[nt][1] * inv0);
    *(float2*)(Og + 8 * D + nt * 8) = make_float2(O[nt][2] * inv1, O[nt][3] * inv1);
  }
}

// ---------------------------------------------------------------------------
extern "C" void kernel_launch(void* const* d_in, const int* in_sizes, int n_in,
                              void* d_out, int out_size) {
  using namespace cfg;
  (void)in_sizes; (void)n_in; (void)out_size;

  const float* query = (const float*)d_in[0];
  const float* key   = (const float*)d_in[1];
  const float* value = (const float*)d_in[2];
  const int* kpm     = (const int*)d_in[3];
  const float* mask  = (const float*)d_in[4];
  const float* Wq    = (const float*)d_in[5];
  const float* Wk    = (const float*)d_in[6];
  const float* Wv    = (const float*)d_in[7];
  const float* Wo    = (const float*)d_in[8];
  float* out = (float*)d_out;

  float *Qp, *Kp, *Vp, *Ap;
  cudaGetSymbolAddress((void**)&Qp, g_Q);
  cudaGetSymbolAddress((void**)&Kp, g_K);
  cudaGetSymbolAddress((void**)&Vp, g_V);
  cudaGetSymbolAddress((void**)&Ap, g_A);

  cudaFuncSetAttribute(gemm_mma_kernel,
                       cudaFuncAttributeMaxDynamicSharedMemorySize, goff::TOTAL);
  cudaFuncSetAttribute(attn_mma_kernel,
                       cudaFuncAttributeMaxDynamicSharedMemorySize, aoff::TOTAL);

  dim3 gg(D / 128, M / 128);  // (8, 32)
  gemm_mma_kernel<<<gg, 256, goff::TOTAL>>>(query, Wq, Qp);
  gemm_mma_kernel<<<gg, 256, goff::TOTAL>>>(key,   Wk, Kp);
  gemm_mma_kernel<<<gg, 256, goff::TOTAL>>>(value, Wv, Vp);

  attn_mma_kernel<<<dim3(L / 64, H, B), 128, aoff::TOTAL>>>(mask, kpm);

  gemm_mma_kernel<<<gg, 256, goff::TOTAL>>>(Ap, Wo, out);
}